// round 6
// baseline (speedup 1.0000x reference)
#include <cuda_runtime.h>
#include <math.h>

// Problem constants
#define BB 2
#define SS 2048
#define HH 1024
#define NHEADS 16
#define DH 64
#define MM (BB * SS)   // 4096 rows

// ---------------- scratch (device globals; no allocation allowed) -----------
__device__ float    g_q[MM * HH];     // projection outputs (tf32-rounded bits)
__device__ float    g_k[MM * HH];
__device__ float    g_v[MM * HH];
__device__ float    g_ctx[MM * HH];   // flash output (tf32-rounded bits)
__device__ unsigned g_qi[MM * HH];    // pre-rounded activations
__device__ unsigned g_ki[MM * HH];
__device__ unsigned g_vi[MM * HH];
__device__ unsigned g_wq[HH * HH];    // pre-rounded weights
__device__ unsigned g_wk[HH * HH];
__device__ unsigned g_wv[HH * HH];
__device__ unsigned g_wo[HH * HH];

// ---------------- helpers ----------------------------------------------------
__device__ __forceinline__ unsigned f2tf(float x) {
    unsigned u;
    asm("cvt.rna.tf32.f32 %0, %1;" : "=r"(u) : "f"(x));
    return u;
}

__device__ __forceinline__ void mma_tf32(float c[4],
                                         unsigned a0, unsigned a1,
                                         unsigned a2, unsigned a3,
                                         unsigned b0, unsigned b1) {
    asm volatile(
        "mma.sync.aligned.m16n8k8.row.col.f32.tf32.tf32.f32 "
        "{%0,%1,%2,%3}, {%4,%5,%6,%7}, {%8,%9}, {%0,%1,%2,%3};"
        : "+f"(c[0]), "+f"(c[1]), "+f"(c[2]), "+f"(c[3])
        : "r"(a0), "r"(a1), "r"(a2), "r"(a3), "r"(b0), "r"(b1));
}

__device__ __forceinline__ void cpa16(unsigned sdst, const void* gsrc) {
    asm volatile("cp.async.cg.shared.global [%0], [%1], 16;"
                 :: "r"(sdst), "l"(gsrc));
}
__device__ __forceinline__ void cpa_commit() {
    asm volatile("cp.async.commit_group;");
}
__device__ __forceinline__ void cpa_wait1() {
    asm volatile("cp.async.wait_group 1;");
}

// ---------------- prepass: round fp32 -> tf32 bits ---------------------------
__global__ __launch_bounds__(256) void round_pass(const float4* __restrict__ in,
                                                  uint4* __restrict__ out, int n4)
{
    int i = blockIdx.x * blockDim.x + threadIdx.x;
    if (i < n4) {
        float4 v = in[i];
        out[i] = make_uint4(f2tf(v.x), f2tf(v.y), f2tf(v.z), f2tf(v.w));
    }
}

// ---------------- GEMM body: C = (A[4096,1024] @ W + bias) * scale ----------
// 128x128 block tile, BK=16, 8 warps (2Mx4N), warp tile 64x32.
// Operands are PRE-ROUNDED tf32 bits; inner loop is pure LDS + MMA.
#define GBM 128
#define GBN 128
#define GBK 16
#define ASTR 36
#define BSTR 136
#define GEMM_SMEM ((2 * GBM * ASTR + 2 * GBK * BSTR) * 4)

__device__ __forceinline__ void gemm_body(
    const unsigned* __restrict__ A, const unsigned* __restrict__ W,
    const float* __restrict__ bias, float* __restrict__ C,
    float scale, int round_out)
{
    extern __shared__ unsigned gsm[];
    unsigned* As = gsm;                       // [2][128][ASTR]
    unsigned* Bs = gsm + 2 * GBM * ASTR;      // [2][16][BSTR]
    const unsigned sb = (unsigned)__cvta_generic_to_shared(gsm);
    const unsigned sbB = sb + 2 * GBM * ASTR * 4;

    const int tid = threadIdx.x;
    const int lane = tid & 31;
    const int wid = tid >> 5;
    const int wm = (wid & 1) * 64;
    const int wn = (wid >> 1) * 32;
    const int r4 = lane >> 2;
    const int c4 = lane & 3;
    const int bm = blockIdx.y * GBM;
    const int bn = blockIdx.x * GBN;

    const int arow = tid >> 1;            // 0..127
    const int ac = (tid & 1) * 8;         // 0 or 8
    const int brow = tid >> 4;            // 0..15
    const int bc = (tid & 15) * 8;        // 0..120

    const unsigned* asrc0 = &A[(size_t)(bm + arow) * HH + ac];

    float acc[16][4];
#pragma unroll
    for (int i = 0; i < 16; i++)
#pragma unroll
        for (int j = 0; j < 4; j++) acc[i][j] = 0.0f;

    const int nk = HH / GBK;

    // prologue: tile 0
    cpa16(sb + (arow * ASTR + ac) * 4, asrc0);
    cpa16(sb + (arow * ASTR + ac + 4) * 4, asrc0 + 4);
    cpa16(sbB + (brow * BSTR + bc) * 4, &W[(size_t)brow * HH + bn + bc]);
    cpa16(sbB + (brow * BSTR + bc + 4) * 4, &W[(size_t)brow * HH + bn + bc + 4]);
    cpa_commit();

    for (int kt = 0; kt < nk; kt++) {
        const int buf = kt & 1;
        const int abuf = buf * GBM * ASTR;
        const int bbuf = buf * GBK * BSTR;
        if (kt + 1 < nk) {
            const int k0 = (kt + 1) * GBK;
            const int nb = (kt + 1) & 1;
            cpa16(sb + (nb * GBM * ASTR + arow * ASTR + ac) * 4, asrc0 + k0);
            cpa16(sb + (nb * GBM * ASTR + arow * ASTR + ac + 4) * 4, asrc0 + k0 + 4);
            cpa16(sbB + (nb * GBK * BSTR + brow * BSTR + bc) * 4,
                  &W[(size_t)(k0 + brow) * HH + bn + bc]);
            cpa16(sbB + (nb * GBK * BSTR + brow * BSTR + bc + 4) * 4,
                  &W[(size_t)(k0 + brow) * HH + bn + bc + 4]);
        }
        cpa_commit();
        cpa_wait1();
        __syncthreads();

#pragma unroll
        for (int ks = 0; ks < 2; ks++) {
            const int kb = ks * 8;
            unsigned bf[4][2];
#pragma unroll
            for (int nt = 0; nt < 4; nt++) {
                const int n = wn + nt * 8 + r4;
                bf[nt][0] = Bs[bbuf + (kb + c4) * BSTR + n];
                bf[nt][1] = Bs[bbuf + (kb + c4 + 4) * BSTR + n];
            }
#pragma unroll
            for (int mt = 0; mt < 4; mt++) {
                const int m = wm + mt * 16 + r4;
                unsigned a0 = As[abuf + m * ASTR + kb + c4];
                unsigned a1 = As[abuf + (m + 8) * ASTR + kb + c4];
                unsigned a2 = As[abuf + m * ASTR + kb + c4 + 4];
                unsigned a3 = As[abuf + (m + 8) * ASTR + kb + c4 + 4];
#pragma unroll
                for (int nt = 0; nt < 4; nt++)
                    mma_tf32(acc[mt * 4 + nt], a0, a1, a2, a3, bf[nt][0], bf[nt][1]);
            }
        }
        __syncthreads();
    }

    // epilogue
#pragma unroll
    for (int mt = 0; mt < 4; mt++) {
#pragma unroll
        for (int nt = 0; nt < 4; nt++) {
            const int row0 = bm + wm + mt * 16 + r4;
            const int col = bn + wn + nt * 8 + 2 * c4;
            float* c0 = &C[(size_t)row0 * HH + col];
            float* c1 = &C[(size_t)(row0 + 8) * HH + col];
            const float b0 = bias[col], b1 = bias[col + 1];
            float v00 = (acc[mt * 4 + nt][0] + b0) * scale;
            float v01 = (acc[mt * 4 + nt][1] + b1) * scale;
            float v10 = (acc[mt * 4 + nt][2] + b0) * scale;
            float v11 = (acc[mt * 4 + nt][3] + b1) * scale;
            if (round_out) {
                c0[0] = __uint_as_float(f2tf(v00));
                c0[1] = __uint_as_float(f2tf(v01));
                c1[0] = __uint_as_float(f2tf(v10));
                c1[1] = __uint_as_float(f2tf(v11));
            } else {
                c0[0] = v00; c0[1] = v01;
                c1[0] = v10; c1[1] = v11;
            }
        }
    }
}

// fused Q/K/V projection: grid.z selects the matrix
__global__ __launch_bounds__(256) void gemm_qkv(
    const unsigned* Aq, const unsigned* Ak, const unsigned* Av,
    const unsigned* Wq, const unsigned* Wk, const unsigned* Wv,
    const float* bq, const float* bk, const float* bv,
    float* Cq, float* Ck, float* Cv)
{
    const int z = blockIdx.z;
    const unsigned* A = (z == 0) ? Aq : (z == 1) ? Ak : Av;
    const unsigned* W = (z == 0) ? Wq : (z == 1) ? Wk : Wv;
    const float* bias = (z == 0) ? bq : (z == 1) ? bk : bv;
    float* C = (z == 0) ? Cq : (z == 1) ? Ck : Cv;
    const float scale = (z == 0) ? 0.125f : 1.0f;
    gemm_body(A, W, bias, C, scale, 1);
}

__global__ __launch_bounds__(256) void gemm_out(
    const unsigned* A, const unsigned* W, const float* bias, float* C)
{
    gemm_body(A, W, bias, C, 1.0f, 0);
}

// ---------------- Flash attention (tf32 mma) ---------------------------------
// grid (S/64, NHEADS, B), 128 threads = 4 warps, each warp owns 16 q rows.
// Q fragments in registers (pre-rounded bits, loaded once). K/V double-
// buffered via cp.async (pre-rounded). P overlays the current K buffer.
#define FQS 68   // K/P stride (==4 mod 32)
#define FVS 72   // V stride   (==8 mod 32)
#define FLASH_SMEM ((2 * 64 * FQS + 2 * 64 * FVS) * 4)

__global__ __launch_bounds__(128) void flash_tf32(
    const unsigned* __restrict__ Q, const unsigned* __restrict__ K,
    const unsigned* __restrict__ V, const float* __restrict__ mask,
    float* __restrict__ Ctx)
{
    extern __shared__ unsigned fsm[];
    unsigned* Ks = fsm;                         // [2][64][FQS] (P overlays cur buf)
    unsigned* Vs = fsm + 2 * 64 * FQS;          // [2][64][FVS]
    const unsigned sb = (unsigned)__cvta_generic_to_shared(fsm);
    const unsigned sbV = sb + 2 * 64 * FQS * 4;

    const int tid = threadIdx.x;
    const int lane = tid & 31;
    const int w = tid >> 5;
    const int r4 = lane >> 2;
    const int c4 = lane & 3;
    const int qb = blockIdx.x * 64;
    const int h = blockIdx.y;
    const int b = blockIdx.z;

    const size_t base = (size_t)b * SS * HH;
    const int hoff = h * DH;
    const float* maskb = mask + (size_t)b * SS * SS;

    const int srow = tid >> 1;            // 0..63
    const int scol0 = (tid & 1) * 32;     // 0 or 32

    // prologue: issue K/V tile 0 copies
    {
        const unsigned* kp = &K[base + (size_t)srow * HH + hoff + scol0];
        const unsigned* vp = &V[base + (size_t)srow * HH + hoff + scol0];
#pragma unroll
        for (int j = 0; j < 8; j++) {
            cpa16(sb + (srow * FQS + scol0 + j * 4) * 4, kp + j * 4);
            cpa16(sbV + (srow * FVS + scol0 + j * 4) * 4, vp + j * 4);
        }
        cpa_commit();
    }

    // load Q fragments (pre-rounded tf32 bits)
    unsigned qf[8][4];
    {
        const size_t R0 = base + (size_t)(qb + 16 * w + r4) * HH + hoff;
#pragma unroll
        for (int ks = 0; ks < 8; ks++) {
            qf[ks][0] = Q[R0 + ks * 8 + c4];
            qf[ks][1] = Q[R0 + 8 * HH + ks * 8 + c4];
            qf[ks][2] = Q[R0 + ks * 8 + c4 + 4];
            qf[ks][3] = Q[R0 + 8 * HH + ks * 8 + c4 + 4];
        }
    }

    float oc[8][4];
#pragma unroll
    for (int nt = 0; nt < 8; nt++)
#pragma unroll
        for (int j = 0; j < 4; j++) oc[nt][j] = 0.0f;
    float m0 = -1e30f, m1 = -1e30f, l0 = 0.0f, l1 = 0.0f;

    const int NT = SS / 64;
    for (int t = 0; t < NT; t++) {
        const int k0 = t * 64;
        const int kbuf = (t & 1) * 64 * FQS;
        const int vbuf = (t & 1) * 64 * FVS;

        if (t + 1 < NT) {
            const int nb = (t + 1) & 1;
            const unsigned* kp = &K[base + (size_t)(k0 + 64 + srow) * HH + hoff + scol0];
            const unsigned* vp = &V[base + (size_t)(k0 + 64 + srow) * HH + hoff + scol0];
#pragma unroll
            for (int j = 0; j < 8; j++) {
                cpa16(sb + (nb * 64 * FQS + srow * FQS + scol0 + j * 4) * 4, kp + j * 4);
                cpa16(sbV + (nb * 64 * FVS + srow * FVS + scol0 + j * 4) * 4, vp + j * 4);
            }
        }
        cpa_commit();
        cpa_wait1();
        __syncthreads();

        // ---- S = Q @ K^T (warp: 16q x 64k) ----
        float sc[8][4];
#pragma unroll
        for (int nt = 0; nt < 8; nt++)
#pragma unroll
            for (int j = 0; j < 4; j++) sc[nt][j] = 0.0f;

#pragma unroll
        for (int ks = 0; ks < 8; ks++) {
            const int kb = ks * 8;
#pragma unroll
            for (int nt = 0; nt < 8; nt++) {
                unsigned b0 = Ks[kbuf + (nt * 8 + r4) * FQS + kb + c4];
                unsigned b1 = Ks[kbuf + (nt * 8 + r4) * FQS + kb + c4 + 4];
                mma_tf32(sc[nt], qf[ks][0], qf[ks][1], qf[ks][2], qf[ks][3], b0, b1);
            }
        }

        // ---- mask + online softmax ----
        {
            const size_t mb0 = (size_t)(qb + 16 * w + r4) * SS + k0 + 2 * c4;
            const size_t mb1 = mb0 + (size_t)8 * SS;
#pragma unroll
            for (int nt = 0; nt < 8; nt++) {
                const float2 m0v = *(const float2*)&maskb[mb0 + nt * 8];
                const float2 m1v = *(const float2*)&maskb[mb1 + nt * 8];
                sc[nt][0] += m0v.x; sc[nt][1] += m0v.y;
                sc[nt][2] += m1v.x; sc[nt][3] += m1v.y;
            }
        }
        float tm0 = -1e30f, tm1 = -1e30f;
#pragma unroll
        for (int nt = 0; nt < 8; nt++) {
            tm0 = fmaxf(tm0, fmaxf(sc[nt][0], sc[nt][1]));
            tm1 = fmaxf(tm1, fmaxf(sc[nt][2], sc[nt][3]));
        }
#pragma unroll
        for (int o = 1; o <= 2; o <<= 1) {
            tm0 = fmaxf(tm0, __shfl_xor_sync(0xffffffffu, tm0, o));
            tm1 = fmaxf(tm1, __shfl_xor_sync(0xffffffffu, tm1, o));
        }
        const float nm0 = fmaxf(m0, tm0), nm1 = fmaxf(m1, tm1);
        float s0 = 0.0f, s1 = 0.0f;
#pragma unroll
        for (int nt = 0; nt < 8; nt++) {
            sc[nt][0] = __expf(sc[nt][0] - nm0);
            sc[nt][1] = __expf(sc[nt][1] - nm0);
            sc[nt][2] = __expf(sc[nt][2] - nm1);
            sc[nt][3] = __expf(sc[nt][3] - nm1);
            s0 += sc[nt][0] + sc[nt][1];
            s1 += sc[nt][2] + sc[nt][3];
        }
#pragma unroll
        for (int o = 1; o <= 2; o <<= 1) {
            s0 += __shfl_xor_sync(0xffffffffu, s0, o);
            s1 += __shfl_xor_sync(0xffffffffu, s1, o);
        }
        const float e0 = __expf(m0 - nm0), e1 = __expf(m1 - nm1);
        l0 = l0 * e0 + s0; m0 = nm0;
        l1 = l1 * e1 + s1; m1 = nm1;
#pragma unroll
        for (int nt = 0; nt < 8; nt++) {
            oc[nt][0] *= e0; oc[nt][1] *= e0;
            oc[nt][2] *= e1; oc[nt][3] *= e1;
        }

        // all warps must finish reading K[kbuf] before P overwrites it
        __syncthreads();

        // ---- stage P (rounded) into current K buffer, warp-private rows ----
        {
            const int pr = kbuf + (16 * w + r4) * FQS;
#pragma unroll
            for (int nt = 0; nt < 8; nt++) {
                *(uint2*)&Ks[pr + nt * 8 + 2 * c4] =
                    make_uint2(f2tf(sc[nt][0]), f2tf(sc[nt][1]));
                *(uint2*)&Ks[pr + 8 * FQS + nt * 8 + 2 * c4] =
                    make_uint2(f2tf(sc[nt][2]), f2tf(sc[nt][3]));
            }
        }
        __syncwarp();

        // ---- O += P @ V ----
#pragma unroll
        for (int ks = 0; ks < 8; ks++) {
            const int kb = ks * 8;
            const int pr = kbuf + (16 * w + r4) * FQS;
            unsigned a0 = Ks[pr + kb + c4];
            unsigned a1 = Ks[pr + 8 * FQS + kb + c4];
            unsigned a2 = Ks[pr + kb + c4 + 4];
            unsigned a3 = Ks[pr + 8 * FQS + kb + c4 + 4];
#pragma unroll
            for (int nt = 0; nt < 8; nt++) {
                unsigned b0 = Vs[vbuf + (kb + c4) * FVS + nt * 8 + r4];
                unsigned b1 = Vs[vbuf + (kb + c4 + 4) * FVS + nt * 8 + r4];
                mma_tf32(oc[nt], a0, a1, a2, a3, b0, b1);
            }
        }
        // protect K/V buffers (and P region) before next iteration's prefetch
        __syncthreads();
    }

    // epilogue: normalize, write ctx as tf32-rounded bits
    const float il0 = 1.0f / l0, il1 = 1.0f / l1;
    const size_t R0c = base + (size_t)(qb + 16 * w + r4) * HH + hoff;
#pragma unroll
    for (int nt = 0; nt < 8; nt++) {
        const int col = nt * 8 + 2 * c4;
        *(float2*)&Ctx[R0c + col] = make_float2(
            __uint_as_float(f2tf(oc[nt][0] * il0)),
            __uint_as_float(f2tf(oc[nt][1] * il0)));
        *(float2*)&Ctx[R0c + 8 * HH + col] = make_float2(
            __uint_as_float(f2tf(oc[nt][2] * il1)),
            __uint_as_float(f2tf(oc[nt][3] * il1)));
    }
}

// ---------------- launch -----------------------------------------------------
extern "C" void kernel_launch(void* const* d_in, const int* in_sizes, int n_in,
                              void* d_out, int out_size)
{
    const float* key   = (const float*)d_in[0];
    const float* value = (const float*)d_in[1];
    const float* query = (const float*)d_in[2];
    const float* mask  = (const float*)d_in[3];
    const float* Wq    = (const float*)d_in[4];
    const float* bq    = (const float*)d_in[5];
    const float* Wk    = (const float*)d_in[6];
    const float* bk    = (const float*)d_in[7];
    const float* Wv    = (const float*)d_in[8];
    const float* bv    = (const float*)d_in[9];
    const float* Wo    = (const float*)d_in[10];
    const float* bo    = (const float*)d_in[11];
    float* out = (float*)d_out;

    float *gq, *gk, *gv, *gctx;
    unsigned *gqi, *gki, *gvi, *gwq, *gwk, *gwv, *gwo;
    cudaGetSymbolAddress((void**)&gq, g_q);
    cudaGetSymbolAddress((void**)&gk, g_k);
    cudaGetSymbolAddress((void**)&gv, g_v);
    cudaGetSymbolAddress((void**)&gctx, g_ctx);
    cudaGetSymbolAddress((void**)&gqi, g_qi);
    cudaGetSymbolAddress((void**)&gki, g_ki);
    cudaGetSymbolAddress((void**)&gvi, g_vi);
    cudaGetSymbolAddress((void**)&gwq, g_wq);
    cudaGetSymbolAddress((void**)&gwk, g_wk);
    cudaGetSymbolAddress((void**)&gwv, g_wv);
    cudaGetSymbolAddress((void**)&gwo, g_wo);

    cudaFuncSetAttribute(gemm_qkv,
                         cudaFuncAttributeMaxDynamicSharedMemorySize, GEMM_SMEM);
    cudaFuncSetAttribute(gemm_out,
                         cudaFuncAttributeMaxDynamicSharedMemorySize, GEMM_SMEM);
    cudaFuncSetAttribute(flash_tf32,
                         cudaFuncAttributeMaxDynamicSharedMemorySize, FLASH_SMEM);

    // prepass: round activations + weights to tf32 bits
    const int nact4 = MM * HH / 4;   // 1M float4
    const int nw4 = HH * HH / 4;     // 256K float4
    round_pass<<<(nact4 + 255) / 256, 256>>>((const float4*)query, (uint4*)gqi, nact4);
    round_pass<<<(nact4 + 255) / 256, 256>>>((const float4*)key,   (uint4*)gki, nact4);
    round_pass<<<(nact4 + 255) / 256, 256>>>((const float4*)value, (uint4*)gvi, nact4);
    round_pass<<<(nw4 + 255) / 256, 256>>>((const float4*)Wq, (uint4*)gwq, nw4);
    round_pass<<<(nw4 + 255) / 256, 256>>>((const float4*)Wk, (uint4*)gwk, nw4);
    round_pass<<<(nw4 + 255) / 256, 256>>>((const float4*)Wv, (uint4*)gwv, nw4);
    round_pass<<<(nw4 + 255) / 256, 256>>>((const float4*)Wo, (uint4*)gwo, nw4);

    // fused Q/K/V projections (outputs tf32-rounded; Q gets 1/sqrt(dh))
    dim3 qkvgrid(HH / GBN, MM / GBM, 3);   // (8, 32, 3)
    gemm_qkv<<<qkvgrid, 256, GEMM_SMEM>>>(gqi, gki, gvi, gwq, gwk, gwv,
                                          bq, bk, bv, gq, gk, gv);

    // attention
    dim3 fgrid(SS / 64, NHEADS, BB);       // (32, 16, 2)
    flash_tf32<<<fgrid, 128, FLASH_SMEM>>>((const unsigned*)gq, (const unsigned*)gk,
                                           (const unsigned*)gv, mask, gctx);

    // output projection (fp32 out)
    dim3 ogrid(HH / GBN, MM / GBM);        // (8, 32)
    gemm_out<<<ogrid, 256, GEMM_SMEM>>>((const unsigned*)gctx, gwo, bo, out);
}

// round 8
// speedup vs baseline: 1.1502x; 1.1502x over previous
#include <cuda_runtime.h>
#include <math.h>

// Problem constants
#define BB 2
#define SS 2048
#define HH 1024
#define NHEADS 16
#define DH 64
#define MM (BB * SS)   // 4096 rows

// ---------------- scratch (device globals; no allocation allowed) -----------
__device__ float g_q[MM * HH];
__device__ float g_k[MM * HH];
__device__ float g_v[MM * HH];
__device__ float g_ctx[MM * HH];

// ---------------- helpers ----------------------------------------------------
__device__ __forceinline__ unsigned f2tf(float x) {
    unsigned u;
    asm("cvt.rna.tf32.f32 %0, %1;" : "=r"(u) : "f"(x));
    return u;
}
// round raw fp32 bits (from smem) to tf32
__device__ __forceinline__ unsigned b2tf(unsigned bits) {
    unsigned u;
    asm("cvt.rna.tf32.f32 %0, %1;" : "=r"(u) : "f"(__uint_as_float(bits)));
    return u;
}

__device__ __forceinline__ void mma_tf32(float c[4],
                                         unsigned a0, unsigned a1,
                                         unsigned a2, unsigned a3,
                                         unsigned b0, unsigned b1) {
    asm volatile(
        "mma.sync.aligned.m16n8k8.row.col.f32.tf32.tf32.f32 "
        "{%0,%1,%2,%3}, {%4,%5,%6,%7}, {%8,%9}, {%0,%1,%2,%3};"
        : "+f"(c[0]), "+f"(c[1]), "+f"(c[2]), "+f"(c[3])
        : "r"(a0), "r"(a1), "r"(a2), "r"(a3), "r"(b0), "r"(b1));
}

__device__ __forceinline__ void cpa16(unsigned sdst, const void* gsrc) {
    asm volatile("cp.async.cg.shared.global [%0], [%1], 16;"
                 :: "r"(sdst), "l"(gsrc));
}
__device__ __forceinline__ void cpa_commit() {
    asm volatile("cp.async.commit_group;");
}
__device__ __forceinline__ void cpa_wait1() {
    asm volatile("cp.async.wait_group 1;");
}

// ---------------- GEMM: C = (A[M,K] @ W[K,N] + bias) * scale ----------------
// (Round-5 version: known good, 88us each.)
#define GBM 128
#define GBN 128
#define GBK 16
#define ASTR 36
#define BSTR 136
#define GEMM_SMEM ((2 * GBM * ASTR + 2 * GBK * BSTR) * 4)

__global__ __launch_bounds__(256) void gemm_tf32(
    const float* __restrict__ A, const float* __restrict__ W,
    const float* __restrict__ bias, float* __restrict__ C,
    int M, int N, int Kd, float scale)
{
    extern __shared__ unsigned gsm[];
    unsigned* As = gsm;                       // [2][128][ASTR] raw fp32 bits
    unsigned* Bs = gsm + 2 * GBM * ASTR;      // [2][16][BSTR]
    const unsigned sb = (unsigned)__cvta_generic_to_shared(gsm);
    const unsigned sbB = sb + 2 * GBM * ASTR * 4;

    const int tid = threadIdx.x;
    const int lane = tid & 31;
    const int wid = tid >> 5;
    const int wm = (wid & 1) * 64;
    const int wn = (wid >> 1) * 32;
    const int r4 = lane >> 2;
    const int c4 = lane & 3;
    const int bm = blockIdx.y * GBM;
    const int bn = blockIdx.x * GBN;

    const int arow = tid >> 1;            // 0..127
    const int ac = (tid & 1) * 8;         // 0 or 8
    const int brow = tid >> 4;            // 0..15
    const int bc = (tid & 15) * 8;        // 0..120

    const float* asrc0 = &A[(size_t)(bm + arow) * Kd + ac];

    float acc[16][4];
#pragma unroll
    for (int i = 0; i < 16; i++)
#pragma unroll
        for (int j = 0; j < 4; j++) acc[i][j] = 0.0f;

    const int nk = Kd / GBK;

    // prologue: tile 0
    {
        cpa16(sb + (arow * ASTR + ac) * 4, asrc0);
        cpa16(sb + (arow * ASTR + ac + 4) * 4, asrc0 + 4);
        cpa16(sbB + (brow * BSTR + bc) * 4, &W[(size_t)brow * N + bn + bc]);
        cpa16(sbB + (brow * BSTR + bc + 4) * 4, &W[(size_t)brow * N + bn + bc + 4]);
        cpa_commit();
    }

    for (int kt = 0; kt < nk; kt++) {
        const int buf = kt & 1;
        const int abuf = buf * GBM * ASTR;
        const int bbuf = buf * GBK * BSTR;
        if (kt + 1 < nk) {
            const int k0 = (kt + 1) * GBK;
            const int nb = (kt + 1) & 1;
            cpa16(sb + (nb * GBM * ASTR + arow * ASTR + ac) * 4, asrc0 + k0);
            cpa16(sb + (nb * GBM * ASTR + arow * ASTR + ac + 4) * 4, asrc0 + k0 + 4);
            cpa16(sbB + (nb * GBK * BSTR + brow * BSTR + bc) * 4,
                  &W[(size_t)(k0 + brow) * N + bn + bc]);
            cpa16(sbB + (nb * GBK * BSTR + brow * BSTR + bc + 4) * 4,
                  &W[(size_t)(k0 + brow) * N + bn + bc + 4]);
        }
        cpa_commit();
        cpa_wait1();
        __syncthreads();

#pragma unroll
        for (int ks = 0; ks < 2; ks++) {
            const int kb = ks * 8;
            unsigned bf[4][2];
#pragma unroll
            for (int nt = 0; nt < 4; nt++) {
                const int n = wn + nt * 8 + r4;
                bf[nt][0] = b2tf(Bs[bbuf + (kb + c4) * BSTR + n]);
                bf[nt][1] = b2tf(Bs[bbuf + (kb + c4 + 4) * BSTR + n]);
            }
#pragma unroll
            for (int mt = 0; mt < 4; mt++) {
                const int m = wm + mt * 16 + r4;
                unsigned a0 = b2tf(As[abuf + m * ASTR + kb + c4]);
                unsigned a1 = b2tf(As[abuf + (m + 8) * ASTR + kb + c4]);
                unsigned a2 = b2tf(As[abuf + m * ASTR + kb + c4 + 4]);
                unsigned a3 = b2tf(As[abuf + (m + 8) * ASTR + kb + c4 + 4]);
#pragma unroll
                for (int nt = 0; nt < 4; nt++)
                    mma_tf32(acc[mt * 4 + nt], a0, a1, a2, a3, bf[nt][0], bf[nt][1]);
            }
        }
        __syncthreads();
    }

    // epilogue
#pragma unroll
    for (int mt = 0; mt < 4; mt++) {
#pragma unroll
        for (int nt = 0; nt < 4; nt++) {
            const int row0 = bm + wm + mt * 16 + r4;
            const int col = bn + wn + nt * 8 + 2 * c4;
            float* c0 = &C[(size_t)row0 * N + col];
            float* c1 = &C[(size_t)(row0 + 8) * N + col];
            const float b0 = bias[col], b1 = bias[col + 1];
            c0[0] = (acc[mt * 4 + nt][0] + b0) * scale;
            c0[1] = (acc[mt * 4 + nt][1] + b1) * scale;
            c1[0] = (acc[mt * 4 + nt][2] + b0) * scale;
            c1[1] = (acc[mt * 4 + nt][3] + b1) * scale;
        }
    }
}

// ---------------- Flash attention (tf32 mma) ---------------------------------
// grid (S/128, NHEADS, B), 256 threads = 8 warps, each warp owns 16 q rows.
// Same tiling/traffic as Round 5 but per-thread state halved -> no spills,
// and 2 CTAs/SM now give 16 warps/SM.
#define FBQ 128
#define QSTR 68   // K buffer stride (==4 mod 32)
#define VSTR 72   // V buffer stride (==8 mod 32)
#define PSTR 68
#define FLASH_SMEM ((2 * 64 * QSTR + 2 * 64 * VSTR + FBQ * PSTR) * 4)

__global__ __launch_bounds__(256, 2) void flash_tf32(
    const float* __restrict__ Q, const float* __restrict__ K,
    const float* __restrict__ V, const float* __restrict__ mask,
    float* __restrict__ Ctx)
{
    extern __shared__ unsigned fsm[];
    unsigned* Ks = fsm;                         // [2][64][QSTR] raw fp32
    unsigned* Vs = fsm + 2 * 64 * QSTR;         // [2][64][VSTR] raw fp32
    unsigned* Ps = Vs + 2 * 64 * VSTR;          // [128][PSTR]   tf32
    const unsigned sb = (unsigned)__cvta_generic_to_shared(fsm);
    const unsigned sbV = sb + 2 * 64 * QSTR * 4;

    const int tid = threadIdx.x;
    const int lane = tid & 31;
    const int w = tid >> 5;               // 0..7
    const int r4 = lane >> 2;
    const int c4 = lane & 3;
    const int qb = blockIdx.x * FBQ;
    const int h = blockIdx.y;
    const int b = blockIdx.z;

    const size_t base = (size_t)b * SS * HH;
    const int hoff = h * DH;
    const float* maskb = mask + (size_t)b * SS * SS;

    // staging: 256 threads cover 64x64 K and V tiles, 4 cpa16 each per tile
    const int srow = tid >> 2;            // 0..63
    const int scol0 = (tid & 3) * 16;     // 0,16,32,48

    // prologue: issue K/V tile 0 copies
    {
        const float* kp = &K[base + (size_t)srow * HH + hoff + scol0];
        const float* vp = &V[base + (size_t)srow * HH + hoff + scol0];
#pragma unroll
        for (int j = 0; j < 4; j++) {
            cpa16(sb + (srow * QSTR + scol0 + j * 4) * 4, kp + j * 4);
            cpa16(sbV + (srow * VSTR + scol0 + j * 4) * 4, vp + j * 4);
        }
        cpa_commit();
    }

    // load Q fragments (rounded once; scaled by 0.125 in projection)
    unsigned qf[8][4];
    {
        const size_t R0 = base + (size_t)(qb + 16 * w + r4) * HH + hoff;
#pragma unroll
        for (int ks = 0; ks < 8; ks++) {
            qf[ks][0] = f2tf(Q[R0 + ks * 8 + c4]);
            qf[ks][1] = f2tf(Q[R0 + 8 * HH + ks * 8 + c4]);
            qf[ks][2] = f2tf(Q[R0 + ks * 8 + c4 + 4]);
            qf[ks][3] = f2tf(Q[R0 + 8 * HH + ks * 8 + c4 + 4]);
        }
    }

    float oc[8][4];
#pragma unroll
    for (int nt = 0; nt < 8; nt++)
#pragma unroll
        for (int j = 0; j < 4; j++) oc[nt][j] = 0.0f;
    float m0 = -1e30f, m1 = -1e30f, l0 = 0.0f, l1 = 0.0f;

    const int NT = SS / 64;
    for (int t = 0; t < NT; t++) {
        const int k0 = t * 64;
        const int kbuf = (t & 1) * 64 * QSTR;
        const int vbuf = (t & 1) * 64 * VSTR;

        if (t + 1 < NT) {
            const int nb = (t + 1) & 1;
            const float* kp = &K[base + (size_t)(k0 + 64 + srow) * HH + hoff + scol0];
            const float* vp = &V[base + (size_t)(k0 + 64 + srow) * HH + hoff + scol0];
#pragma unroll
            for (int j = 0; j < 4; j++) {
                cpa16(sb + (nb * 64 * QSTR + srow * QSTR + scol0 + j * 4) * 4, kp + j * 4);
                cpa16(sbV + (nb * 64 * VSTR + srow * VSTR + scol0 + j * 4) * 4, vp + j * 4);
            }
        }
        cpa_commit();
        cpa_wait1();
        __syncthreads();

        // ---- S = Q @ K^T (warp: 16q x 64k) ----
        float sc[8][4];
#pragma unroll
        for (int nt = 0; nt < 8; nt++)
#pragma unroll
            for (int j = 0; j < 4; j++) sc[nt][j] = 0.0f;

#pragma unroll
        for (int ks = 0; ks < 8; ks++) {
            const int kb = ks * 8;
#pragma unroll
            for (int nt = 0; nt < 8; nt++) {
                unsigned b0 = b2tf(Ks[kbuf + (nt * 8 + r4) * QSTR + kb + c4]);
                unsigned b1 = b2tf(Ks[kbuf + (nt * 8 + r4) * QSTR + kb + c4 + 4]);
                mma_tf32(sc[nt], qf[ks][0], qf[ks][1], qf[ks][2], qf[ks][3], b0, b1);
            }
        }

        // ---- mask + online softmax ----
        {
            const size_t mb0 = (size_t)(qb + 16 * w + r4) * SS + k0 + 2 * c4;
            const size_t mb1 = mb0 + (size_t)8 * SS;
#pragma unroll
            for (int nt = 0; nt < 8; nt++) {
                const float2 m0v = *(const float2*)&maskb[mb0 + nt * 8];
                const float2 m1v = *(const float2*)&maskb[mb1 + nt * 8];
                sc[nt][0] += m0v.x; sc[nt][1] += m0v.y;
                sc[nt][2] += m1v.x; sc[nt][3] += m1v.y;
            }
        }
        float tm0 = -1e30f, tm1 = -1e30f;
#pragma unroll
        for (int nt = 0; nt < 8; nt++) {
            tm0 = fmaxf(tm0, fmaxf(sc[nt][0], sc[nt][1]));
            tm1 = fmaxf(tm1, fmaxf(sc[nt][2], sc[nt][3]));
        }
#pragma unroll
        for (int o = 1; o <= 2; o <<= 1) {
            tm0 = fmaxf(tm0, __shfl_xor_sync(0xffffffffu, tm0, o));
            tm1 = fmaxf(tm1, __shfl_xor_sync(0xffffffffu, tm1, o));
        }
        const float nm0 = fmaxf(m0, tm0), nm1 = fmaxf(m1, tm1);
        float s0 = 0.0f, s1 = 0.0f;
#pragma unroll
        for (int nt = 0; nt < 8; nt++) {
            sc[nt][0] = __expf(sc[nt][0] - nm0);
            sc[nt][1] = __expf(sc[nt][1] - nm0);
            sc[nt][2] = __expf(sc[nt][2] - nm1);
            sc[nt][3] = __expf(sc[nt][3] - nm1);
            s0 += sc[nt][0] + sc[nt][1];
            s1 += sc[nt][2] + sc[nt][3];
        }
#pragma unroll
        for (int o = 1; o <= 2; o <<= 1) {
            s0 += __shfl_xor_sync(0xffffffffu, s0, o);
            s1 += __shfl_xor_sync(0xffffffffu, s1, o);
        }
        const float e0 = __expf(m0 - nm0), e1 = __expf(m1 - nm1);
        l0 = l0 * e0 + s0; m0 = nm0;
        l1 = l1 * e1 + s1; m1 = nm1;
#pragma unroll
        for (int nt = 0; nt < 8; nt++) {
            oc[nt][0] *= e0; oc[nt][1] *= e0;
            oc[nt][2] *= e1; oc[nt][3] *= e1;
        }

        // ---- stage P rounded to tf32 (warp-private rows; no block sync) ----
        {
            const int pr = (16 * w + r4) * PSTR;
#pragma unroll
            for (int nt = 0; nt < 8; nt++) {
                *(uint2*)&Ps[pr + nt * 8 + 2 * c4] =
                    make_uint2(f2tf(sc[nt][0]), f2tf(sc[nt][1]));
                *(uint2*)&Ps[pr + 8 * PSTR + nt * 8 + 2 * c4] =
                    make_uint2(f2tf(sc[nt][2]), f2tf(sc[nt][3]));
            }
        }
        __syncwarp();

        // ---- O += P @ V ----
#pragma unroll
        for (int ks = 0; ks < 8; ks++) {
            const int kb = ks * 8;
            const int pr = (16 * w + r4) * PSTR;
            unsigned a0 = Ps[pr + kb + c4];
            unsigned a1 = Ps[pr + 8 * PSTR + kb + c4];
            unsigned a2 = Ps[pr + kb + c4 + 4];
            unsigned a3 = Ps[pr + 8 * PSTR + kb + c4 + 4];
#pragma unroll
            for (int nt = 0; nt < 8; nt++) {
                unsigned b0 = b2tf(Vs[vbuf + (kb + c4) * VSTR + nt * 8 + r4]);
                unsigned b1 = b2tf(Vs[vbuf + (kb + c4 + 4) * VSTR + nt * 8 + r4]);
                mma_tf32(oc[nt], a0, a1, a2, a3, b0, b1);
            }
        }
        // protect K/V buffers before next iteration's prefetch overwrites
        __syncthreads();
    }

    // epilogue: normalize, write ctx in [B,S,heads*dh]
    const float il0 = 1.0f / l0, il1 = 1.0f / l1;
    const size_t R0c = base + (size_t)(qb + 16 * w + r4) * HH + hoff;
#pragma unroll
    for (int nt = 0; nt < 8; nt++) {
        const int col = nt * 8 + 2 * c4;
        *(float2*)&Ctx[R0c + col] =
            make_float2(oc[nt][0] * il0, oc[nt][1] * il0);
        *(float2*)&Ctx[R0c + 8 * HH + col] =
            make_float2(oc[nt][2] * il1, oc[nt][3] * il1);
    }
}

// ---------------- launch -----------------------------------------------------
extern "C" void kernel_launch(void* const* d_in, const int* in_sizes, int n_in,
                              void* d_out, int out_size)
{
    const float* key   = (const float*)d_in[0];
    const float* value = (const float*)d_in[1];
    const float* query = (const float*)d_in[2];
    const float* mask  = (const float*)d_in[3];
    const float* Wq    = (const float*)d_in[4];
    const float* bq    = (const float*)d_in[5];
    const float* Wk    = (const float*)d_in[6];
    const float* bk    = (const float*)d_in[7];
    const float* Wv    = (const float*)d_in[8];
    const float* bv    = (const float*)d_in[9];
    const float* Wo    = (const float*)d_in[10];
    const float* bo    = (const float*)d_in[11];
    float* out = (float*)d_out;

    float *gq, *gk, *gv, *gctx;
    cudaGetSymbolAddress((void**)&gq, g_q);
    cudaGetSymbolAddress((void**)&gk, g_k);
    cudaGetSymbolAddress((void**)&gv, g_v);
    cudaGetSymbolAddress((void**)&gctx, g_ctx);
    cudaFuncSetAttribute(gemm_tf32,
                         cudaFuncAttributeMaxDynamicSharedMemorySize, GEMM_SMEM);
    cudaFuncSetAttribute(flash_tf32,
                         cudaFuncAttributeMaxDynamicSharedMemorySize, FLASH_SMEM);

    dim3 ggrid(HH / GBN, MM / GBM);   // (8, 32)

    gemm_tf32<<<ggrid, 256, GEMM_SMEM>>>(query, Wq, bq, gq, MM, HH, HH, 0.125f);
    gemm_tf32<<<ggrid, 256, GEMM_SMEM>>>(key,   Wk, bk, gk, MM, HH, HH, 1.0f);
    gemm_tf32<<<ggrid, 256, GEMM_SMEM>>>(value, Wv, bv, gv, MM, HH, HH, 1.0f);

    dim3 fgrid(SS / FBQ, NHEADS, BB); // (16, 16, 2)
    flash_tf32<<<fgrid, 256, FLASH_SMEM>>>(gq, gk, gv, mask, gctx);

    gemm_tf32<<<ggrid, 256, GEMM_SMEM>>>(gctx, Wo, bo, out, MM, HH, HH, 1.0f);
}